// round 2
// baseline (speedup 1.0000x reference)
#include <cuda_runtime.h>
#include <cuda_bf16.h>

#define SEQ   4096
#define DM    1024
#define NOUT  864      // 12 * 72
#define NIMU  72
#define TSTEPS 300
#define PLANE (NIMU*SEQ)   // 294912

typedef unsigned long long ull;

// -------- scratch (static device memory; no runtime allocs) --------
__device__ __align__(16) float g_xn[SEQ * DM];          // 16 MB  layernorm output
__device__ __align__(16) float g_p [SEQ * NOUT];        // 14 MB  GEMM output
__device__ __align__(16) float g_prm[SEQ * NIMU * 8];   // 9.4 MB recurrence params

__device__ __forceinline__ ull ffma2(ull a, ull b, ull c) {
    ull d;
    asm("fma.rn.f32x2 %0, %1, %2, %3;" : "=l"(d) : "l"(a), "l"(b), "l"(c));
    return d;
}

__device__ __forceinline__ float softplusf(float x) {
    // matches jax.nn.softplus = max(x,0) + log1p(exp(-|x|))
    return fmaxf(x, 0.0f) + log1pf(expf(-fabsf(x)));
}

// ============================ LayerNorm ============================
__global__ void ln_kernel(const float* __restrict__ hs,
                          const float* __restrict__ gamma,
                          const float* __restrict__ beta) {
    int row = blockIdx.x;
    int tid = threadIdx.x;                 // 256 threads, 4 floats each
    const float4* xr = (const float4*)(hs + (size_t)row * DM);
    float4 v = xr[tid];
    float s  = v.x + v.y + v.z + v.w;
    float ss = v.x*v.x + v.y*v.y + v.z*v.z + v.w*v.w;
    #pragma unroll
    for (int o = 16; o > 0; o >>= 1) {
        s  += __shfl_xor_sync(0xffffffffu, s,  o);
        ss += __shfl_xor_sync(0xffffffffu, ss, o);
    }
    __shared__ float2 part[8];
    __shared__ float2 mv;
    int w = tid >> 5, l = tid & 31;
    if (l == 0) part[w] = make_float2(s, ss);
    __syncthreads();
    if (tid == 0) {
        float S = 0.f, SS = 0.f;
        #pragma unroll
        for (int i = 0; i < 8; ++i) { S += part[i].x; SS += part[i].y; }
        float mu  = S * (1.0f / DM);
        float var = SS * (1.0f / DM) - mu * mu;
        mv = make_float2(mu, rsqrtf(var + 1e-5f));
    }
    __syncthreads();
    float mu = mv.x, rstd = mv.y;
    float4 g  = ((const float4*)gamma)[tid];
    float4 be = ((const float4*)beta)[tid];
    float4 o;
    o.x = (v.x - mu) * rstd * g.x + be.x;
    o.y = (v.y - mu) * rstd * g.y + be.y;
    o.z = (v.z - mu) * rstd * g.z + be.z;
    o.w = (v.w - mu) * rstd * g.w + be.w;
    ((float4*)(g_xn + (size_t)row * DM))[tid] = o;
}

// ============================ GEMM =================================
// C(4096x864) = xn(4096x1024) @ W(1024x864) + b
// BM=128 BN=96 BK=16, 256 threads, micro-tile 8m x 6n per thread,
// accumulators packed as m-pairs in f32x2. B staged duplicated {b,b}.
__global__ __launch_bounds__(256) void gemm_kernel(const float* __restrict__ W,
                                                   const float* __restrict__ bias) {
    __shared__ __align__(16) float  As[16][132];   // padded vs bank conflicts
    __shared__ __align__(16) float2 Bs[16][100];   // duplicated pairs, padded

    int tid = threadIdx.x;
    int n0 = blockIdx.x * 96;
    int m0 = blockIdx.y * 128;
    int tx = tid & 15, ty = tid >> 4;

    // A staging map: 512 float4 loads (2/thread)
    int fa0 = tid,        ma0 = fa0 >> 2, ka0 = (fa0 & 3) << 2;
    int fa1 = tid + 256,  ma1 = fa1 >> 2, ka1 = (fa1 & 3) << 2;
    // B staging map: 384 float4 loads (1 or 2/thread)
    int kb0 = tid / 24,        nb0 = (tid % 24) * 4;
    int f2  = tid + 256;
    int kb1 = f2 / 24,         nb1 = (f2 % 24) * 4;
    bool hasB1 = (tid < 128);

    float4 rA0, rA1, rB0, rB1;
    rB1 = make_float4(0.f, 0.f, 0.f, 0.f);
    {   // prefetch tile 0
        rA0 = *(const float4*)(g_xn + (size_t)(m0 + ma0) * DM + ka0);
        rA1 = *(const float4*)(g_xn + (size_t)(m0 + ma1) * DM + ka1);
        rB0 = *(const float4*)(W + (size_t)kb0 * NOUT + n0 + nb0);
        if (hasB1) rB1 = *(const float4*)(W + (size_t)kb1 * NOUT + n0 + nb1);
    }

    ull acc[4][6];
    #pragma unroll
    for (int i = 0; i < 4; ++i)
        #pragma unroll
        for (int j = 0; j < 6; ++j) acc[i][j] = 0ull;

    for (int kt = 0; kt < 64; ++kt) {
        // stage current tile
        As[ka0+0][ma0] = rA0.x; As[ka0+1][ma0] = rA0.y;
        As[ka0+2][ma0] = rA0.z; As[ka0+3][ma0] = rA0.w;
        As[ka1+0][ma1] = rA1.x; As[ka1+1][ma1] = rA1.y;
        As[ka1+2][ma1] = rA1.z; As[ka1+3][ma1] = rA1.w;
        Bs[kb0][nb0+0] = make_float2(rB0.x, rB0.x);
        Bs[kb0][nb0+1] = make_float2(rB0.y, rB0.y);
        Bs[kb0][nb0+2] = make_float2(rB0.z, rB0.z);
        Bs[kb0][nb0+3] = make_float2(rB0.w, rB0.w);
        if (hasB1) {
            Bs[kb1][nb1+0] = make_float2(rB1.x, rB1.x);
            Bs[kb1][nb1+1] = make_float2(rB1.y, rB1.y);
            Bs[kb1][nb1+2] = make_float2(rB1.z, rB1.z);
            Bs[kb1][nb1+3] = make_float2(rB1.w, rB1.w);
        }
        __syncthreads();

        if (kt < 63) {   // prefetch next tile (overlaps compute)
            int k0 = (kt + 1) * 16;
            rA0 = *(const float4*)(g_xn + (size_t)(m0 + ma0) * DM + k0 + ka0);
            rA1 = *(const float4*)(g_xn + (size_t)(m0 + ma1) * DM + k0 + ka1);
            rB0 = *(const float4*)(W + (size_t)(k0 + kb0) * NOUT + n0 + nb0);
            if (hasB1) rB1 = *(const float4*)(W + (size_t)(k0 + kb1) * NOUT + n0 + nb1);
        }

        #pragma unroll
        for (int kk = 0; kk < 16; ++kk) {
            const ulonglong2* ap = (const ulonglong2*)&As[kk][ty << 3];
            ulonglong2 a01 = ap[0], a23 = ap[1];
            const ull* bp = (const ull*)(&Bs[kk][0]);
            #pragma unroll
            for (int j = 0; j < 6; ++j) {
                ull bb = bp[tx + (j << 4)];
                acc[0][j] = ffma2(a01.x, bb, acc[0][j]);
                acc[1][j] = ffma2(a01.y, bb, acc[1][j]);
                acc[2][j] = ffma2(a23.x, bb, acc[2][j]);
                acc[3][j] = ffma2(a23.y, bb, acc[3][j]);
            }
        }
        __syncthreads();
    }

    // epilogue: unpack m-pairs, add bias
    #pragma unroll
    for (int j = 0; j < 6; ++j) {
        int n = n0 + tx + (j << 4);
        float bj = bias[n];
        #pragma unroll
        for (int mp = 0; mp < 4; ++mp) {
            ull a = acc[mp][j];
            float fx = __uint_as_float((unsigned)(a & 0xffffffffull));
            float fy = __uint_as_float((unsigned)(a >> 32));
            int m = m0 + (ty << 3) + (mp << 1);
            g_p[(size_t)m * NOUT + n]       = fx + bj;
            g_p[(size_t)(m + 1) * NOUT + n] = fy + bj;
        }
    }
}

// ===================== Parameter transform =========================
// omega1 = sqrt(4k - d^2)/2 simplifies exactly to sqrt(softplus(p0)).
// Emit complex recurrence seeds u0 = c*e^{i phi}, ratio rho = e^{-d/2} e^{i omega}.
__global__ void transform_kernel(float* __restrict__ out) {
    int g = blockIdx.x * blockDim.x + threadIdx.x;   // 0 .. 294911 exactly
    int s   = g / NIMU;
    int imu = g - s * NIMU;
    const float* pr = g_p + (size_t)s * NOUT + imu;
    float p0  = pr[0 * NIMU], p1  = pr[1 * NIMU], p2  = pr[2 * NIMU], p3  = pr[3 * NIMU];
    float p4  = pr[4 * NIMU], p5  = pr[5 * NIMU], p6  = pr[6 * NIMU], p7  = pr[7 * NIMU];
    float p8  = pr[8 * NIMU], p9  = pr[9 * NIMU], p10 = pr[10 * NIMU], p11 = pr[11 * NIMU];

    float d1  = softplusf(p1);
    float om1 = sqrtf(softplusf(p0));
    float d2  = softplusf(p3);
    float om2 = sqrtf(softplusf(p2));

    float sph1, cph1; sincosf(p6, &sph1, &cph1);
    float sph2, cph2; sincosf(p7, &sph2, &cph2);
    float so1, co1;   sincosf(om1, &so1, &co1);
    float so2, co2;   sincosf(om2, &so2, &co2);
    float e1 = expf(-0.5f * d1);
    float e2 = expf(-0.5f * d2);

    float4 pa = make_float4(p4 * cph1, p4 * sph1, e1 * co1, e1 * so1);
    float4 pb = make_float4(p5 * cph2, p5 * sph2, e2 * co2, e2 * so2);
    float4* pp = (float4*)g_prm;
    pp[g * 2 + 0] = pa;
    pp[g * 2 + 1] = pb;

    int ob = imu * SEQ + s;   // transposed outputs
    out[1 * PLANE + ob] = p8;                // acc_base
    out[2 * PLANE + ob] = softplusf(p9);     // acc_std
    out[3 * PLANE + ob] = p10;               // gyro_base
    out[4 * PLANE + ob] = softplusf(p11);    // gyro_std
}

// ======================= Spring scatter ============================
// block = (t0-chunk of 256, imu). Warp-private smem accumulators:
// lane i at step t hits slot i+t -> distinct addresses within the
// lockstep warp. MUST be volatile: without it ptxas batches the
// unrolled LDS before neighbor lanes' STS from the previous step,
// dropping accumulations (R1 failure, rel_err 0.92).
__global__ __launch_bounds__(256) void spring_kernel(float* __restrict__ kin) {
    __shared__ float buf[8][336];   // per-warp window [32 lanes + 299 steps]
    int tid = threadIdx.x;
    int imu = blockIdx.y;
    int c0  = blockIdx.x * 256;

    for (int i = tid; i < 8 * 336; i += 256) ((float*)buf)[i] = 0.f;
    __syncthreads();

    int t0 = c0 + tid;
    const float4* pp = (const float4*)g_prm;
    float4 pa = pp[((size_t)t0 * NIMU + imu) * 2 + 0];
    float4 pb = pp[((size_t)t0 * NIMU + imu) * 2 + 1];
    float u1r = pa.x, u1i = pa.y, r1r = pa.z, r1i = pa.w;
    float u2r = pb.x, u2i = pb.y, r2r = pb.z, r2i = pb.w;

    volatile float* wb = buf[tid >> 5];
    int l = tid & 31;

    #pragma unroll 4
    for (int t = 0; t < TSTEPS; ++t) {
        wb[l + t] = wb[l + t] + (u1i + u2i);
        float n1r = fmaf(u1r, r1r, -(u1i * r1i));
        float n1i = fmaf(u1r, r1i,  (u1i * r1r));
        float n2r = fmaf(u2r, r2r, -(u2i * r2i));
        float n2i = fmaf(u2r, r2i,  (u2i * r2r));
        u1r = n1r; u1i = n1i; u2r = n2r; u2i = n2i;
    }
    __syncthreads();

    // merge 8 overlapping warp windows -> block output span [c0, c0+554]
    for (int o = tid; o < 555; o += 256) {
        float v = 0.f;
        #pragma unroll
        for (int w = 0; w < 8; ++w) {
            int idx = o - (w << 5);
            if (idx >= 0 && idx <= 330) v += buf[w][idx];
        }
        int pos = c0 + o;
        if (pos < SEQ) atomicAdd(kin + (size_t)imu * SEQ + pos, v);
    }
}

// =========================== launch ================================
extern "C" void kernel_launch(void* const* d_in, const int* in_sizes, int n_in,
                              void* d_out, int out_size) {
    const float* hs    = (const float*)d_in[0];
    const float* gamma = (const float*)d_in[1];
    const float* beta  = (const float*)d_in[2];
    const float* W     = (const float*)d_in[3];
    const float* b     = (const float*)d_in[4];
    float* out = (float*)d_out;

    // kinematics region must start at zero (d_out is poisoned)
    cudaMemsetAsync(out, 0, (size_t)PLANE * sizeof(float), 0);

    ln_kernel<<<SEQ, 256>>>(hs, gamma, beta);
    gemm_kernel<<<dim3(NOUT / 96, SEQ / 128), 256>>>(W, b);
    transform_kernel<<<(SEQ * NIMU) / 256, 256>>>(out);
    spring_kernel<<<dim3(SEQ / 256, NIMU), 256>>>(out);
}

// round 4
// speedup vs baseline: 1.1588x; 1.1588x over previous
#include <cuda_runtime.h>
#include <cuda_bf16.h>
#include <cstdint>

#define SEQ    4096
#define DM     1024
#define NOUT   864      // 12 * 72
#define NIMU   72
#define TSTEPS 300
#define PLANE  (NIMU*SEQ)   // 294912

// GEMM tiling (mma.sync m16n8k16 bf16)
#define BM     128
#define BN     96
#define BK     32
#define NIT    (DM/BK)          // 32 k-chunks
#define APITCH 80               // 32 bf16 = 64B, padded to 80B (conflict-free ldmatrix)
#define R_AHI  0
#define R_ALO  (128*APITCH)                 // 10240
#define R_BHI  (2*128*APITCH)               // 20480
#define R_BLO  (2*128*APITCH + 96*APITCH)   // 28160
#define STAGE  (R_BLO + 96*APITCH)          // 35840
#define SMEM_TOT (2*STAGE)                  // 71680
#define NCOPY  1792   // 16B cp.async per stage: A 2*512 + B 2*384

typedef unsigned long long ull;

// -------- scratch (static device memory; no runtime allocs) --------
__device__ __align__(16) __nv_bfloat16 g_ahi[SEQ * DM];     // LN output hi
__device__ __align__(16) __nv_bfloat16 g_alo[SEQ * DM];     // LN output lo
__device__ __align__(16) __nv_bfloat16 g_whi[NOUT * DM];    // W^T hi
__device__ __align__(16) __nv_bfloat16 g_wlo[NOUT * DM];    // W^T lo
__device__ __align__(16) float g_p  [SEQ * NOUT];           // GEMM output
__device__ __align__(16) float g_prm[SEQ * NIMU * 8];       // recurrence params

// ======================= PTX helpers ===============================
__device__ __forceinline__ uint32_t smem_to_u32(const void* p) {
    uint32_t a;
    asm("{ .reg .u64 t; cvta.to.shared.u64 t, %1; cvt.u32.u64 %0, t; }" : "=r"(a) : "l"(p));
    return a;
}
#define CP_COMMIT() asm volatile("cp.async.commit_group;" ::: "memory")
#define CP_WAIT1()  asm volatile("cp.async.wait_group 1;" ::: "memory")
__device__ __forceinline__ void cpasync16(uint32_t dst, const void* src) {
    asm volatile("cp.async.cg.shared.global [%0], [%1], 16;" :: "r"(dst), "l"(src) : "memory");
}
#define LDSM_X4(r0, r1, r2, r3, addr) \
    asm volatile("ldmatrix.sync.aligned.m8n8.x4.shared.b16 {%0,%1,%2,%3}, [%4];" \
                 : "=r"(r0), "=r"(r1), "=r"(r2), "=r"(r3) : "r"(addr))
#define MMA16816(d, a, b) \
    asm volatile("mma.sync.aligned.m16n8k16.row.col.f32.bf16.bf16.f32 " \
                 "{%0,%1,%2,%3}, {%4,%5,%6,%7}, {%8,%9}, {%0,%1,%2,%3};" \
                 : "+f"((d)[0]), "+f"((d)[1]), "+f"((d)[2]), "+f"((d)[3]) \
                 : "r"((a)[0]), "r"((a)[1]), "r"((a)[2]), "r"((a)[3]), \
                   "r"((b)[0]), "r"((b)[1]))

__device__ __forceinline__ ull ffma2(ull a, ull b, ull c) {
    ull d; asm("fma.rn.f32x2 %0, %1, %2, %3;" : "=l"(d) : "l"(a), "l"(b), "l"(c)); return d;
}
__device__ __forceinline__ ull fmul2(ull a, ull b) {
    ull d; asm("mul.rn.f32x2 %0, %1, %2;" : "=l"(d) : "l"(a), "l"(b)); return d;
}
__device__ __forceinline__ ull fpack2(float lo, float hi) {
    ull d; asm("mov.b64 %0, {%1, %2};" : "=l"(d) : "f"(lo), "f"(hi)); return d;
}
__device__ __forceinline__ float2 funpack2(ull v) {
    float lo, hi; asm("mov.b64 {%0, %1}, %2;" : "=f"(lo), "=f"(hi) : "l"(v));
    return make_float2(lo, hi);
}
__device__ __forceinline__ float softplusf(float x) {
    return fmaxf(x, 0.0f) + log1pf(expf(-fabsf(x)));
}

// ============================ LayerNorm ============================
// Emits bf16 hi/lo split of xn directly (feeds mma.sync GEMM).
__global__ void ln_kernel(const float* __restrict__ hs,
                          const float* __restrict__ gamma,
                          const float* __restrict__ beta) {
    int row = blockIdx.x;
    int tid = threadIdx.x;                 // 256 threads, 4 floats each
    const float4* xr = (const float4*)(hs + (size_t)row * DM);
    float4 v = xr[tid];
    float s  = v.x + v.y + v.z + v.w;
    float ss = v.x*v.x + v.y*v.y + v.z*v.z + v.w*v.w;
    #pragma unroll
    for (int o = 16; o > 0; o >>= 1) {
        s  += __shfl_xor_sync(0xffffffffu, s,  o);
        ss += __shfl_xor_sync(0xffffffffu, ss, o);
    }
    __shared__ float2 part[8];
    __shared__ float2 mv;
    int w = tid >> 5, l = tid & 31;
    if (l == 0) part[w] = make_float2(s, ss);
    __syncthreads();
    if (tid == 0) {
        float S = 0.f, SS = 0.f;
        #pragma unroll
        for (int i = 0; i < 8; ++i) { S += part[i].x; SS += part[i].y; }
        float mu  = S * (1.0f / DM);
        float var = SS * (1.0f / DM) - mu * mu;
        mv = make_float2(mu, rsqrtf(var + 1e-5f));
    }
    __syncthreads();
    float mu = mv.x, rstd = mv.y;
    float4 g  = ((const float4*)gamma)[tid];
    float4 be = ((const float4*)beta)[tid];
    float o0 = (v.x - mu) * rstd * g.x + be.x;
    float o1 = (v.y - mu) * rstd * g.y + be.y;
    float o2 = (v.z - mu) * rstd * g.z + be.z;
    float o3 = (v.w - mu) * rstd * g.w + be.w;

    __nv_bfloat16 h0 = __float2bfloat16_rn(o0), h1 = __float2bfloat16_rn(o1);
    __nv_bfloat16 h2 = __float2bfloat16_rn(o2), h3 = __float2bfloat16_rn(o3);
    __nv_bfloat16 l0 = __float2bfloat16_rn(o0 - __bfloat162float(h0));
    __nv_bfloat16 l1 = __float2bfloat16_rn(o1 - __bfloat162float(h1));
    __nv_bfloat16 l2 = __float2bfloat16_rn(o2 - __bfloat162float(h2));
    __nv_bfloat16 l3 = __float2bfloat16_rn(o3 - __bfloat162float(h3));

    __nv_bfloat162* ph = (__nv_bfloat162*)(g_ahi + (size_t)row * DM);
    __nv_bfloat162* pl = (__nv_bfloat162*)(g_alo + (size_t)row * DM);
    __nv_bfloat162 a, b2;
    a.x = h0; a.y = h1; b2.x = h2; b2.y = h3;
    ph[2*tid] = a; ph[2*tid+1] = b2;
    a.x = l0; a.y = l1; b2.x = l2; b2.y = l3;
    pl[2*tid] = a; pl[2*tid+1] = b2;
}

// ================== W transpose + bf16 split =======================
__global__ void wt_kernel(const float* __restrict__ W) {
    __shared__ float tile[32][33];
    int n0 = blockIdx.x * 32, k0 = blockIdx.y * 32;
    int tx = threadIdx.x, ty = threadIdx.y;   // 32 x 8
    #pragma unroll
    for (int j = 0; j < 4; ++j)
        tile[ty + 8*j][tx] = W[(size_t)(k0 + ty + 8*j) * NOUT + n0 + tx];
    __syncthreads();
    #pragma unroll
    for (int j = 0; j < 4; ++j) {
        float v = tile[tx][ty + 8*j];
        __nv_bfloat16 h = __float2bfloat16_rn(v);
        size_t o = (size_t)(n0 + ty + 8*j) * DM + k0 + tx;
        g_whi[o] = h;
        g_wlo[o] = __float2bfloat16_rn(v - __bfloat162float(h));
    }
}

// ================ mma.sync bf16-split GEMM =========================
// g_p = Ahi*Bhi + Alo*Bhi + Ahi*Blo (fp32 accum) + bias
// 8 warps: warp grid 4(m) x 2(n); warp tile 32m x 48n; k16 per HMMA.
__global__ __launch_bounds__(256, 2) void gemm_kernel(const float* __restrict__ bias) {
    extern __shared__ char smem[];
    uint32_t sb = smem_to_u32(smem);
    int tid = threadIdx.x, wid = tid >> 5, lane = tid & 31;
    int n0 = blockIdx.x * BN, m0 = blockIdx.y * BM;

    // ---- cp.async staging of one 35.8KB chunk (A hi/lo, B hi/lo) ----
    auto stage = [&](int ch, int s) {
        uint32_t base = sb + s * STAGE;
        int kb = ch * BK;
        #pragma unroll
        for (int v = 0; v < NCOPY / 256; ++v) {
            int idx = tid + v * 256;
            const void* src; uint32_t off;
            if (idx < 1024) {                       // A: 2 mats x 128 rows x 4 vec16
                int mat = idx >> 9;
                int i = idx & 511;
                int r = i >> 2, c = i & 3;
                const __nv_bfloat16* g = mat ? g_alo : g_ahi;
                src = g + (size_t)(m0 + r) * DM + kb + c * 8;
                off = (mat ? R_ALO : R_AHI) + r * APITCH + c * 16;
            } else {                                // B: 2 mats x 96 rows x 4 vec16
                int b = idx - 1024;
                int mat = b / 384; int rb = b - mat * 384;
                int r = rb >> 2, c = rb & 3;
                const __nv_bfloat16* g = mat ? g_wlo : g_whi;
                src = g + (size_t)(n0 + r) * DM + kb + c * 8;
                off = (mat ? R_BLO : R_BHI) + r * APITCH + c * 16;
            }
            cpasync16(base + off, src);
        }
        CP_COMMIT();
    };

    stage(0, 0);
    stage(1, 1);

    int wm = (wid >> 1) * 32;          // warp m-offset in CTA tile
    int wn = (wid & 1) * 48;           // warp n-offset
    // ldmatrix per-lane address components (pitch-80 rows -> conflict-free)
    uint32_t aoff = (uint32_t)(wm + (lane & 15)) * APITCH + (uint32_t)(lane >> 4) * 16;
    uint32_t boff = (uint32_t)(wn + (lane & 7) + ((lane >> 4) & 1) * 8) * APITCH
                  + (uint32_t)((lane >> 3) & 1) * 16;

    float acc[2][6][4];
    #pragma unroll
    for (int i = 0; i < 2; ++i)
        #pragma unroll
        for (int j = 0; j < 6; ++j)
            #pragma unroll
            for (int q = 0; q < 4; ++q) acc[i][j][q] = 0.f;

    for (int it = 0; it < NIT; ++it) {
        CP_WAIT1();
        __syncthreads();
        uint32_t base = sb + (it & 1) * STAGE;
        #pragma unroll
        for (int ki = 0; ki < 2; ++ki) {
            uint32_t ah[2][4], al[2][4], bh[6][2], bl[6][2];
            uint32_t ka = base + ki * 32 + aoff;
            LDSM_X4(ah[0][0], ah[0][1], ah[0][2], ah[0][3], ka + R_AHI);
            LDSM_X4(ah[1][0], ah[1][1], ah[1][2], ah[1][3], ka + R_AHI + 16 * APITCH);
            LDSM_X4(al[0][0], al[0][1], al[0][2], al[0][3], ka + R_ALO);
            LDSM_X4(al[1][0], al[1][1], al[1][2], al[1][3], ka + R_ALO + 16 * APITCH);
            uint32_t kb2 = base + ki * 32 + boff;
            #pragma unroll
            for (int pj = 0; pj < 3; ++pj) {
                LDSM_X4(bh[2*pj][0], bh[2*pj][1], bh[2*pj+1][0], bh[2*pj+1][1],
                        kb2 + R_BHI + pj * 16 * APITCH);
                LDSM_X4(bl[2*pj][0], bl[2*pj][1], bl[2*pj+1][0], bl[2*pj+1][1],
                        kb2 + R_BLO + pj * 16 * APITCH);
            }
            #pragma unroll
            for (int mi = 0; mi < 2; ++mi)
                #pragma unroll
                for (int nj = 0; nj < 6; ++nj) {
                    MMA16816(acc[mi][nj], ah[mi], bh[nj]);
                    MMA16816(acc[mi][nj], al[mi], bh[nj]);
                    MMA16816(acc[mi][nj], ah[mi], bl[nj]);
                }
        }
        __syncthreads();
        if (it + 2 < NIT) stage(it + 2, it & 1);
    }

    // ---- epilogue: frags -> g_p (+bias) ----
    int qr = lane >> 2, qc = (lane & 3) * 2;
    #pragma unroll
    for (int mi = 0; mi < 2; ++mi) {
        int mrow = m0 + wm + mi * 16 + qr;
        float* r0 = g_p + (size_t)mrow * NOUT;
        float* r1 = g_p + (size_t)(mrow + 8) * NOUT;
        #pragma unroll
        for (int nj = 0; nj < 6; ++nj) {
            int n = n0 + wn + nj * 8 + qc;
            float b0 = bias[n], b1 = bias[n + 1];
            float2 v0 = make_float2(acc[mi][nj][0] + b0, acc[mi][nj][1] + b1);
            float2 v1 = make_float2(acc[mi][nj][2] + b0, acc[mi][nj][3] + b1);
            *(float2*)(r0 + n) = v0;
            *(float2*)(r1 + n) = v1;
        }
    }
}

// ===================== Parameter transform =========================
// omega = sqrt(4k - d^2)/2 simplifies exactly to sqrt(softplus(p0)).
__global__ void transform_kernel(float* __restrict__ out) {
    int g = blockIdx.x * blockDim.x + threadIdx.x;   // 0 .. 294911
    int s   = g / NIMU;
    int imu = g - s * NIMU;
    const float* pr = g_p + (size_t)s * NOUT + imu;
    float p0  = pr[0 * NIMU], p1  = pr[1 * NIMU], p2  = pr[2 * NIMU], p3  = pr[3 * NIMU];
    float p4  = pr[4 * NIMU], p5  = pr[5 * NIMU], p6  = pr[6 * NIMU], p7  = pr[7 * NIMU];
    float p8  = pr[8 * NIMU], p9  = pr[9 * NIMU], p10 = pr[10 * NIMU], p11 = pr[11 * NIMU];

    float d1  = softplusf(p1);
    float om1 = sqrtf(softplusf(p0));
    float d2  = softplusf(p3);
    float om2 = sqrtf(softplusf(p2));

    float sph1, cph1; sincosf(p6, &sph1, &cph1);
    float sph2, cph2; sincosf(p7, &sph2, &cph2);
    float so1, co1;   sincosf(om1, &so1, &co1);
    float so2, co2;   sincosf(om2, &so2, &co2);
    float e1 = expf(-0.5f * d1);
    float e2 = expf(-0.5f * d2);

    float4 pa = make_float4(p4 * cph1, p4 * sph1, e1 * co1, e1 * so1);
    float4 pb = make_float4(p5 * cph2, p5 * sph2, e2 * co2, e2 * so2);
    float4* pp = (float4*)g_prm;
    pp[g * 2 + 0] = pa;
    pp[g * 2 + 1] = pb;

    int ob = imu * SEQ + s;   // transposed outputs
    out[1 * PLANE + ob] = p8;
    out[2 * PLANE + ob] = softplusf(p9);
    out[3 * PLANE + ob] = p10;
    out[4 * PLANE + ob] = softplusf(p11);
}

// ======================= Spring scatter ============================
// Warp-private volatile smem windows (lane i, step t -> slot i+t, distinct
// within lockstep warp; volatile forbids cross-iteration LDS batching).
// Both oscillators packed in f32x2.
__global__ __launch_bounds__(256) void spring_kernel(float* __restrict__ kin) {
    __shared__ float buf[8][336];
    int tid = threadIdx.x;
    int imu = blockIdx.y;
    int c0  = blockIdx.x * 256;

    for (int i = tid; i < 8 * 336; i += 256) ((float*)buf)[i] = 0.f;
    __syncthreads();

    int t0 = c0 + tid;
    const float4* pp = (const float4*)g_prm;
    float4 pa = pp[((size_t)t0 * NIMU + imu) * 2 + 0];
    float4 pb = pp[((size_t)t0 * NIMU + imu) * 2 + 1];
    ull Ur  = fpack2(pa.x, pb.x);
    ull Ui  = fpack2(pa.y, pb.y);
    ull Rr  = fpack2(pa.z, pb.z);
    ull Ri  = fpack2(pa.w, pb.w);
    ull Rin = fpack2(-pa.w, -pb.w);

    volatile float* wb = buf[tid >> 5];
    int l = tid & 31;

    #pragma unroll 4
    for (int t = 0; t < TSTEPS; ++t) {
        float2 ui = funpack2(Ui);
        wb[l + t] = wb[l + t] + (ui.x + ui.y);
        ull t1 = fmul2(Ui, Rin);
        ull t2 = fmul2(Ui, Rr);
        ull nr = ffma2(Ur, Rr, t1);
        ull ni = ffma2(Ur, Ri, t2);
        Ur = nr; Ui = ni;
    }
    __syncthreads();

    for (int o = tid; o < 555; o += 256) {
        float v = 0.f;
        #pragma unroll
        for (int w = 0; w < 8; ++w) {
            int idx = o - (w << 5);
            if (idx >= 0 && idx <= 330) v += buf[w][idx];
        }
        int pos = c0 + o;
        if (pos < SEQ) atomicAdd(kin + (size_t)imu * SEQ + pos, v);
    }
}

// =========================== launch ================================
extern "C" void kernel_launch(void* const* d_in, const int* in_sizes, int n_in,
                              void* d_out, int out_size) {
    const float* hs    = (const float*)d_in[0];
    const float* gamma = (const float*)d_in[1];
    const float* beta  = (const float*)d_in[2];
    const float* W     = (const float*)d_in[3];
    const float* b     = (const float*)d_in[4];
    float* out = (float*)d_out;

    cudaFuncSetAttribute(gemm_kernel, cudaFuncAttributeMaxDynamicSharedMemorySize, SMEM_TOT);

    cudaMemsetAsync(out, 0, (size_t)PLANE * sizeof(float), 0);

    ln_kernel<<<SEQ, 256>>>(hs, gamma, beta);
    wt_kernel<<<dim3(NOUT / 32, DM / 32), dim3(32, 8)>>>(W);
    gemm_kernel<<<dim3(NOUT / BN, SEQ / BM), 256, SMEM_TOT>>>(b);
    transform_kernel<<<(SEQ * NIMU) / 256, 256>>>(out);
    spring_kernel<<<dim3(SEQ / 256, NIMU), 256>>>(out);
}

// round 5
// speedup vs baseline: 2.0177x; 1.7412x over previous
#include <cuda_runtime.h>
#include <cuda_bf16.h>
#include <cstdint>

#define SEQ    4096
#define DM     1024
#define NOUT   864      // 12 * 72
#define NIMU   72
#define TSTEPS 300
#define PLANE  (NIMU*SEQ)   // 294912

// GEMM tiling (mma.sync m16n8k16 bf16)
#define BM     128
#define BN     96
#define BK     32
#define NIT    (DM/BK)          // 32 k-chunks
#define APITCH 80               // 32 bf16 = 64B, padded to 80B (conflict-free ldmatrix)
#define R_AHI  0
#define R_ALO  (128*APITCH)                 // 10240
#define R_BHI  (2*128*APITCH)               // 20480
#define R_BLO  (2*128*APITCH + 96*APITCH)   // 28160
#define STAGE  (R_BLO + 96*APITCH)          // 35840
#define SMEM_TOT (2*STAGE)                  // 71680
#define NCOPY  1792   // 16B cp.async per stage: A 2*512 + B 2*384

typedef unsigned long long ull;

// -------- scratch (static device memory; no runtime allocs) --------
__device__ __align__(16) __nv_bfloat16 g_ahi[SEQ * DM];     // LN output hi
__device__ __align__(16) __nv_bfloat16 g_alo[SEQ * DM];     // LN output lo
__device__ __align__(16) __nv_bfloat16 g_whi[NOUT * DM];    // W^T hi
__device__ __align__(16) __nv_bfloat16 g_wlo[NOUT * DM];    // W^T lo
__device__ __align__(16) float g_pT [NOUT * SEQ];           // GEMM output, TRANSPOSED [n][s]

// ======================= PTX helpers ===============================
__device__ __forceinline__ uint32_t smem_to_u32(const void* p) {
    uint32_t a;
    asm("{ .reg .u64 t; cvta.to.shared.u64 t, %1; cvt.u32.u64 %0, t; }" : "=r"(a) : "l"(p));
    return a;
}
#define CP_COMMIT() asm volatile("cp.async.commit_group;" ::: "memory")
#define CP_WAIT1()  asm volatile("cp.async.wait_group 1;" ::: "memory")
__device__ __forceinline__ void cpasync16(uint32_t dst, const void* src) {
    asm volatile("cp.async.cg.shared.global [%0], [%1], 16;" :: "r"(dst), "l"(src) : "memory");
}
#define LDSM_X4(r0, r1, r2, r3, addr) \
    asm volatile("ldmatrix.sync.aligned.m8n8.x4.shared.b16 {%0,%1,%2,%3}, [%4];" \
                 : "=r"(r0), "=r"(r1), "=r"(r2), "=r"(r3) : "r"(addr))
#define MMA16816(d, a, b) \
    asm volatile("mma.sync.aligned.m16n8k16.row.col.f32.bf16.bf16.f32 " \
                 "{%0,%1,%2,%3}, {%4,%5,%6,%7}, {%8,%9}, {%0,%1,%2,%3};" \
                 : "+f"((d)[0]), "+f"((d)[1]), "+f"((d)[2]), "+f"((d)[3]) \
                 : "r"((a)[0]), "r"((a)[1]), "r"((a)[2]), "r"((a)[3]), \
                   "r"((b)[0]), "r"((b)[1]))

__device__ __forceinline__ ull ffma2(ull a, ull b, ull c) {
    ull d; asm("fma.rn.f32x2 %0, %1, %2, %3;" : "=l"(d) : "l"(a), "l"(b), "l"(c)); return d;
}
__device__ __forceinline__ ull fmul2(ull a, ull b) {
    ull d; asm("mul.rn.f32x2 %0, %1, %2;" : "=l"(d) : "l"(a), "l"(b)); return d;
}
__device__ __forceinline__ ull fpack2(float lo, float hi) {
    ull d; asm("mov.b64 %0, {%1, %2};" : "=l"(d) : "f"(lo), "f"(hi)); return d;
}
__device__ __forceinline__ float2 funpack2(ull v) {
    float lo, hi; asm("mov.b64 {%0, %1}, %2;" : "=f"(lo), "=f"(hi) : "l"(v));
    return make_float2(lo, hi);
}
__device__ __forceinline__ float softplusf(float x) {
    return fmaxf(x, 0.0f) + log1pf(expf(-fabsf(x)));
}

// ======================= zero kinematics ===========================
__global__ void zero_kernel(float* __restrict__ out) {
    int i = blockIdx.x * blockDim.x + threadIdx.x;   // PLANE/4 threads
    ((float4*)out)[i] = make_float4(0.f, 0.f, 0.f, 0.f);
}

// ============================ LayerNorm ============================
// Emits bf16 hi/lo split of xn directly (feeds mma.sync GEMM).
__global__ void ln_kernel(const float* __restrict__ hs,
                          const float* __restrict__ gamma,
                          const float* __restrict__ beta) {
    int row = blockIdx.x;
    int tid = threadIdx.x;                 // 256 threads, 4 floats each
    const float4* xr = (const float4*)(hs + (size_t)row * DM);
    float4 v = xr[tid];
    float s  = v.x + v.y + v.z + v.w;
    float ss = v.x*v.x + v.y*v.y + v.z*v.z + v.w*v.w;
    #pragma unroll
    for (int o = 16; o > 0; o >>= 1) {
        s  += __shfl_xor_sync(0xffffffffu, s,  o);
        ss += __shfl_xor_sync(0xffffffffu, ss, o);
    }
    __shared__ float2 part[8];
    __shared__ float2 mv;
    int w = tid >> 5, l = tid & 31;
    if (l == 0) part[w] = make_float2(s, ss);
    __syncthreads();
    if (tid == 0) {
        float S = 0.f, SS = 0.f;
        #pragma unroll
        for (int i = 0; i < 8; ++i) { S += part[i].x; SS += part[i].y; }
        float mu  = S * (1.0f / DM);
        float var = SS * (1.0f / DM) - mu * mu;
        mv = make_float2(mu, rsqrtf(var + 1e-5f));
    }
    __syncthreads();
    float mu = mv.x, rstd = mv.y;
    float4 g  = ((const float4*)gamma)[tid];
    float4 be = ((const float4*)beta)[tid];
    float o0 = (v.x - mu) * rstd * g.x + be.x;
    float o1 = (v.y - mu) * rstd * g.y + be.y;
    float o2 = (v.z - mu) * rstd * g.z + be.z;
    float o3 = (v.w - mu) * rstd * g.w + be.w;

    __nv_bfloat16 h0 = __float2bfloat16_rn(o0), h1 = __float2bfloat16_rn(o1);
    __nv_bfloat16 h2 = __float2bfloat16_rn(o2), h3 = __float2bfloat16_rn(o3);
    __nv_bfloat16 l0 = __float2bfloat16_rn(o0 - __bfloat162float(h0));
    __nv_bfloat16 l1 = __float2bfloat16_rn(o1 - __bfloat162float(h1));
    __nv_bfloat16 l2 = __float2bfloat16_rn(o2 - __bfloat162float(h2));
    __nv_bfloat16 l3 = __float2bfloat16_rn(o3 - __bfloat162float(h3));

    __nv_bfloat162* ph = (__nv_bfloat162*)(g_ahi + (size_t)row * DM);
    __nv_bfloat162* pl = (__nv_bfloat162*)(g_alo + (size_t)row * DM);
    __nv_bfloat162 a, b2;
    a.x = h0; a.y = h1; b2.x = h2; b2.y = h3;
    ph[2*tid] = a; ph[2*tid+1] = b2;
    a.x = l0; a.y = l1; b2.x = l2; b2.y = l3;
    pl[2*tid] = a; pl[2*tid+1] = b2;
}

// ================== W transpose + bf16 split =======================
__global__ void wt_kernel(const float* __restrict__ W) {
    __shared__ float tile[32][33];
    int n0 = blockIdx.x * 32, k0 = blockIdx.y * 32;
    int tx = threadIdx.x, ty = threadIdx.y;   // 32 x 8
    #pragma unroll
    for (int j = 0; j < 4; ++j)
        tile[ty + 8*j][tx] = W[(size_t)(k0 + ty + 8*j) * NOUT + n0 + tx];
    __syncthreads();
    #pragma unroll
    for (int j = 0; j < 4; ++j) {
        float v = tile[tx][ty + 8*j];
        __nv_bfloat16 h = __float2bfloat16_rn(v);
        size_t o = (size_t)(n0 + ty + 8*j) * DM + k0 + tx;
        g_whi[o] = h;
        g_wlo[o] = __float2bfloat16_rn(v - __bfloat162float(h));
    }
}

// ================ mma.sync bf16-split GEMM =========================
// g_pT[n][s] = (Ahi*Bhi + Alo*Bhi + Ahi*Blo)[s][n] + bias[n]
// 8 warps: warp grid 4(m) x 2(n); warp tile 32m x 48n; k16 per HMMA.
__global__ __launch_bounds__(256, 2) void gemm_kernel(const float* __restrict__ bias) {
    extern __shared__ char smem[];
    uint32_t sb = smem_to_u32(smem);
    int tid = threadIdx.x, wid = tid >> 5, lane = tid & 31;
    int n0 = blockIdx.x * BN, m0 = blockIdx.y * BM;

    // ---- cp.async staging of one 35.8KB chunk (A hi/lo, B hi/lo) ----
    auto stage = [&](int ch, int s) {
        uint32_t base = sb + s * STAGE;
        int kb = ch * BK;
        #pragma unroll
        for (int v = 0; v < NCOPY / 256; ++v) {
            int idx = tid + v * 256;
            const void* src; uint32_t off;
            if (idx < 1024) {                       // A: 2 mats x 128 rows x 4 vec16
                int mat = idx >> 9;
                int i = idx & 511;
                int r = i >> 2, c = i & 3;
                const __nv_bfloat16* g = mat ? g_alo : g_ahi;
                src = g + (size_t)(m0 + r) * DM + kb + c * 8;
                off = (mat ? R_ALO : R_AHI) + r * APITCH + c * 16;
            } else {                                // B: 2 mats x 96 rows x 4 vec16
                int b = idx - 1024;
                int mat = b / 384; int rb = b - mat * 384;
                int r = rb >> 2, c = rb & 3;
                const __nv_bfloat16* g = mat ? g_wlo : g_whi;
                src = g + (size_t)(n0 + r) * DM + kb + c * 8;
                off = (mat ? R_BLO : R_BHI) + r * APITCH + c * 16;
            }
            cpasync16(base + off, src);
        }
        CP_COMMIT();
    };

    stage(0, 0);
    stage(1, 1);

    int wm = (wid >> 1) * 32;          // warp m-offset in CTA tile
    int wn = (wid & 1) * 48;           // warp n-offset
    // ldmatrix per-lane address components (pitch-80 rows -> conflict-free)
    uint32_t aoff = (uint32_t)(wm + (lane & 15)) * APITCH + (uint32_t)(lane >> 4) * 16;
    uint32_t boff = (uint32_t)(wn + (lane & 7) + ((lane >> 4) & 1) * 8) * APITCH
                  + (uint32_t)((lane >> 3) & 1) * 16;

    float acc[2][6][4];
    #pragma unroll
    for (int i = 0; i < 2; ++i)
        #pragma unroll
        for (int j = 0; j < 6; ++j)
            #pragma unroll
            for (int q = 0; q < 4; ++q) acc[i][j][q] = 0.f;

    for (int it = 0; it < NIT; ++it) {
        CP_WAIT1();
        __syncthreads();
        uint32_t base = sb + (it & 1) * STAGE;
        #pragma unroll
        for (int ki = 0; ki < 2; ++ki) {
            uint32_t ah[2][4], al[2][4], bh[6][2], bl[6][2];
            uint32_t ka = base + ki * 32 + aoff;
            LDSM_X4(ah[0][0], ah[0][1], ah[0][2], ah[0][3], ka + R_AHI);
            LDSM_X4(ah[1][0], ah[1][1], ah[1][2], ah[1][3], ka + R_AHI + 16 * APITCH);
            LDSM_X4(al[0][0], al[0][1], al[0][2], al[0][3], ka + R_ALO);
            LDSM_X4(al[1][0], al[1][1], al[1][2], al[1][3], ka + R_ALO + 16 * APITCH);
            uint32_t kb2 = base + ki * 32 + boff;
            #pragma unroll
            for (int pj = 0; pj < 3; ++pj) {
                LDSM_X4(bh[2*pj][0], bh[2*pj][1], bh[2*pj+1][0], bh[2*pj+1][1],
                        kb2 + R_BHI + pj * 16 * APITCH);
                LDSM_X4(bl[2*pj][0], bl[2*pj][1], bl[2*pj+1][0], bl[2*pj+1][1],
                        kb2 + R_BLO + pj * 16 * APITCH);
            }
            #pragma unroll
            for (int mi = 0; mi < 2; ++mi)
                #pragma unroll
                for (int nj = 0; nj < 6; ++nj) {
                    MMA16816(acc[mi][nj], ah[mi], bh[nj]);
                    MMA16816(acc[mi][nj], al[mi], bh[nj]);
                    MMA16816(acc[mi][nj], ah[mi], bl[nj]);
                }
        }
        __syncthreads();
        if (it + 2 < NIT) stage(it + 2, it & 1);
    }

    // ---- epilogue: frags -> g_pT (transposed, +bias) ----
    int qr = lane >> 2, qc = (lane & 3) * 2;
    #pragma unroll
    for (int mi = 0; mi < 2; ++mi) {
        int m = m0 + wm + mi * 16 + qr;
        #pragma unroll
        for (int nj = 0; nj < 6; ++nj) {
            int n = n0 + wn + nj * 8 + qc;
            float b0 = bias[n], b1 = bias[n + 1];
            g_pT[(size_t)n       * SEQ + m]     = acc[mi][nj][0] + b0;
            g_pT[(size_t)(n + 1) * SEQ + m]     = acc[mi][nj][1] + b1;
            g_pT[(size_t)n       * SEQ + m + 8] = acc[mi][nj][2] + b0;
            g_pT[(size_t)(n + 1) * SEQ + m + 8] = acc[mi][nj][3] + b1;
        }
    }
}

// ============== Fused transform + spring scatter ===================
// One thread per (t0, imu) site: computes oscillator params (MUFU work
// hidden under the FMA-bound recurrence loop), emits the 4 output
// channels, then runs the 300-step complex recurrence with warp-private
// volatile smem windows (lane i, step t -> slot i+t: distinct within
// lockstep warp; volatile forbids cross-iteration LDS batching).
__global__ __launch_bounds__(256) void spring_kernel(float* __restrict__ out) {
    __shared__ float buf[8][336];
    int tid = threadIdx.x;
    int imu = blockIdx.y;
    int c0  = blockIdx.x * 256;
    int t0  = c0 + tid;

    for (int i = tid; i < 8 * 336; i += 256) ((float*)buf)[i] = 0.f;

    // ---- coalesced param loads from transposed GEMM output ----
    const float* col = g_pT + (size_t)imu * SEQ + t0;   // stride PLANE per noise row
    float p0  = col[0*PLANE],  p1  = col[1*PLANE],  p2  = col[2*PLANE],  p3 = col[3*PLANE];
    float p4  = col[4*PLANE],  p5  = col[5*PLANE],  p6  = col[6*PLANE],  p7 = col[7*PLANE];
    float p8  = col[8*PLANE],  p9  = col[9*PLANE],  p10 = col[10*PLANE], p11 = col[11*PLANE];

    // ---- direct output channels ----
    size_t ob = (size_t)imu * SEQ + t0;
    out[1 * PLANE + ob] = p8;
    out[2 * PLANE + ob] = softplusf(p9);
    out[3 * PLANE + ob] = p10;
    out[4 * PLANE + ob] = softplusf(p11);

    // ---- oscillator params: omega = sqrt(4k-d^2)/2 == sqrt(softplus(p0)) ----
    float om1 = sqrtf(softplusf(p0));
    float e1  = expf(-0.5f * softplusf(p1));
    float om2 = sqrtf(softplusf(p2));
    float e2  = expf(-0.5f * softplusf(p3));
    float sph1, cph1; sincosf(p6, &sph1, &cph1);
    float sph2, cph2; sincosf(p7, &sph2, &cph2);
    float so1, co1;   sincosf(om1, &so1, &co1);
    float so2, co2;   sincosf(om2, &so2, &co2);

    // pack both oscillators into f32x2 lanes
    ull Ur  = fpack2(p4 * cph1, p5 * cph2);
    ull Ui  = fpack2(p4 * sph1, p5 * sph2);
    ull Rr  = fpack2(e1 * co1,  e2 * co2);
    ull Ri  = fpack2(e1 * so1,  e2 * so2);
    ull Rin = fpack2(-e1 * so1, -e2 * so2);

    __syncthreads();

    volatile float* wb = buf[tid >> 5];
    int l = tid & 31;

    #pragma unroll 4
    for (int t = 0; t < TSTEPS; ++t) {
        float2 ui = funpack2(Ui);
        wb[l + t] = wb[l + t] + (ui.x + ui.y);
        ull t1 = fmul2(Ui, Rin);
        ull t2 = fmul2(Ui, Rr);
        ull nr = ffma2(Ur, Rr, t1);
        ull ni = ffma2(Ur, Ri, t2);
        Ur = nr; Ui = ni;
    }
    __syncthreads();

    // merge 8 overlapping warp windows -> block output span [c0, c0+554]
    for (int o = tid; o < 555; o += 256) {
        float v = 0.f;
        #pragma unroll
        for (int w = 0; w < 8; ++w) {
            int idx = o - (w << 5);
            if (idx >= 0 && idx <= 330) v += buf[w][idx];
        }
        int pos = c0 + o;
        if (pos < SEQ) atomicAdd(out + (size_t)imu * SEQ + pos, v);
    }
}

// =========================== launch ================================
extern "C" void kernel_launch(void* const* d_in, const int* in_sizes, int n_in,
                              void* d_out, int out_size) {
    const float* hs    = (const float*)d_in[0];
    const float* gamma = (const float*)d_in[1];
    const float* beta  = (const float*)d_in[2];
    const float* W     = (const float*)d_in[3];
    const float* b     = (const float*)d_in[4];
    float* out = (float*)d_out;

    cudaFuncSetAttribute(gemm_kernel, cudaFuncAttributeMaxDynamicSharedMemorySize, SMEM_TOT);

    zero_kernel<<<PLANE / 1024, 256>>>(out);                       // #1
    ln_kernel<<<SEQ, 256>>>(hs, gamma, beta);                      // #2
    wt_kernel<<<dim3(NOUT / 32, DM / 32), dim3(32, 8)>>>(W);       // #3
    gemm_kernel<<<dim3(NOUT / BN, SEQ / BM), 256, SMEM_TOT>>>(b);  // #4 (ncu target)
    spring_kernel<<<dim3(SEQ / 256, NIMU), 256>>>(out);            // #5
}

// round 6
// speedup vs baseline: 2.0480x; 1.0150x over previous
#include <cuda_runtime.h>
#include <cuda_bf16.h>
#include <cstdint>

#define SEQ    4096
#define DM     1024
#define NOUT   864      // 12 * 72
#define NIMU   72
#define TSTEPS 300
#define PLANE  (NIMU*SEQ)   // 294912

// GEMM tiling (mma.sync m16n8k16 bf16)
#define BM     128
#define BN     96
#define BK     32
#define NIT    (DM/BK)          // 32 k-chunks
#define APITCH 80               // 32 bf16 = 64B, padded to 80B (conflict-free ldmatrix)
#define R_AHI  0
#define R_ALO  (128*APITCH)                 // 10240
#define R_BHI  (2*128*APITCH)               // 20480
#define R_BLO  (2*128*APITCH + 96*APITCH)   // 28160
#define STAGE  (R_BLO + 96*APITCH)          // 35840
#define SMEM_TOT (3*STAGE)                  // 107520 (3-stage ring)
#define NCOPY  1792   // 16B cp.async per stage: A 2*512 + B 2*384

typedef unsigned long long ull;

// -------- scratch (static device memory; no runtime allocs) --------
__device__ __align__(16) __nv_bfloat16 g_ahi[SEQ * DM];     // LN output hi
__device__ __align__(16) __nv_bfloat16 g_alo[SEQ * DM];     // LN output lo
__device__ __align__(16) __nv_bfloat16 g_whi[NOUT * DM];    // W^T hi
__device__ __align__(16) __nv_bfloat16 g_wlo[NOUT * DM];    // W^T lo
__device__ __align__(16) float g_pT [NOUT * SEQ];           // GEMM output, TRANSPOSED [n][s]

// ======================= PTX helpers ===============================
__device__ __forceinline__ uint32_t smem_to_u32(const void* p) {
    uint32_t a;
    asm("{ .reg .u64 t; cvta.to.shared.u64 t, %1; cvt.u32.u64 %0, t; }" : "=r"(a) : "l"(p));
    return a;
}
#define CP_COMMIT() asm volatile("cp.async.commit_group;" ::: "memory")
#define CP_WAIT1()  asm volatile("cp.async.wait_group 1;" ::: "memory")
__device__ __forceinline__ void cpasync16(uint32_t dst, const void* src) {
    asm volatile("cp.async.cg.shared.global [%0], [%1], 16;" :: "r"(dst), "l"(src) : "memory");
}
#define LDSM_X4(r0, r1, r2, r3, addr) \
    asm volatile("ldmatrix.sync.aligned.m8n8.x4.shared.b16 {%0,%1,%2,%3}, [%4];" \
                 : "=r"(r0), "=r"(r1), "=r"(r2), "=r"(r3) : "r"(addr))
#define MMA16816(d, a, b) \
    asm volatile("mma.sync.aligned.m16n8k16.row.col.f32.bf16.bf16.f32 " \
                 "{%0,%1,%2,%3}, {%4,%5,%6,%7}, {%8,%9}, {%0,%1,%2,%3};" \
                 : "+f"((d)[0]), "+f"((d)[1]), "+f"((d)[2]), "+f"((d)[3]) \
                 : "r"((a)[0]), "r"((a)[1]), "r"((a)[2]), "r"((a)[3]), \
                   "r"((b)[0]), "r"((b)[1]))

__device__ __forceinline__ ull ffma2(ull a, ull b, ull c) {
    ull d; asm("fma.rn.f32x2 %0, %1, %2, %3;" : "=l"(d) : "l"(a), "l"(b), "l"(c)); return d;
}
__device__ __forceinline__ ull fmul2(ull a, ull b) {
    ull d; asm("mul.rn.f32x2 %0, %1, %2;" : "=l"(d) : "l"(a), "l"(b)); return d;
}
__device__ __forceinline__ ull fpack2(float lo, float hi) {
    ull d; asm("mov.b64 %0, {%1, %2};" : "=l"(d) : "f"(lo), "f"(hi)); return d;
}
__device__ __forceinline__ float2 funpack2(ull v) {
    float lo, hi; asm("mov.b64 {%0, %1}, %2;" : "=f"(lo), "=f"(hi) : "l"(v));
    return make_float2(lo, hi);
}
__device__ __forceinline__ float softplusf(float x) {
    return fmaxf(x, 0.0f) + log1pf(expf(-fabsf(x)));
}

// ======================= zero kinematics ===========================
__global__ void zero_kernel(float* __restrict__ out) {
    int i = blockIdx.x * blockDim.x + threadIdx.x;   // PLANE/4 threads
    ((float4*)out)[i] = make_float4(0.f, 0.f, 0.f, 0.f);
}

// ============================ LayerNorm ============================
// Emits bf16 hi/lo split of xn directly (feeds mma.sync GEMM).
__global__ void ln_kernel(const float* __restrict__ hs,
                          const float* __restrict__ gamma,
                          const float* __restrict__ beta) {
    int row = blockIdx.x;
    int tid = threadIdx.x;                 // 256 threads, 4 floats each
    const float4* xr = (const float4*)(hs + (size_t)row * DM);
    float4 v = xr[tid];
    float s  = v.x + v.y + v.z + v.w;
    float ss = v.x*v.x + v.y*v.y + v.z*v.z + v.w*v.w;
    #pragma unroll
    for (int o = 16; o > 0; o >>= 1) {
        s  += __shfl_xor_sync(0xffffffffu, s,  o);
        ss += __shfl_xor_sync(0xffffffffu, ss, o);
    }
    __shared__ float2 part[8];
    __shared__ float2 mv;
    int w = tid >> 5, l = tid & 31;
    if (l == 0) part[w] = make_float2(s, ss);
    __syncthreads();
    if (tid == 0) {
        float S = 0.f, SS = 0.f;
        #pragma unroll
        for (int i = 0; i < 8; ++i) { S += part[i].x; SS += part[i].y; }
        float mu  = S * (1.0f / DM);
        float var = SS * (1.0f / DM) - mu * mu;
        mv = make_float2(mu, rsqrtf(var + 1e-5f));
    }
    __syncthreads();
    float mu = mv.x, rstd = mv.y;
    float4 g  = ((const float4*)gamma)[tid];
    float4 be = ((const float4*)beta)[tid];
    float o0 = (v.x - mu) * rstd * g.x + be.x;
    float o1 = (v.y - mu) * rstd * g.y + be.y;
    float o2 = (v.z - mu) * rstd * g.z + be.z;
    float o3 = (v.w - mu) * rstd * g.w + be.w;

    __nv_bfloat16 h0 = __float2bfloat16_rn(o0), h1 = __float2bfloat16_rn(o1);
    __nv_bfloat16 h2 = __float2bfloat16_rn(o2), h3 = __float2bfloat16_rn(o3);
    __nv_bfloat16 l0 = __float2bfloat16_rn(o0 - __bfloat162float(h0));
    __nv_bfloat16 l1 = __float2bfloat16_rn(o1 - __bfloat162float(h1));
    __nv_bfloat16 l2 = __float2bfloat16_rn(o2 - __bfloat162float(h2));
    __nv_bfloat16 l3 = __float2bfloat16_rn(o3 - __bfloat162float(h3));

    __nv_bfloat162* ph = (__nv_bfloat162*)(g_ahi + (size_t)row * DM);
    __nv_bfloat162* pl = (__nv_bfloat162*)(g_alo + (size_t)row * DM);
    __nv_bfloat162 a, b2;
    a.x = h0; a.y = h1; b2.x = h2; b2.y = h3;
    ph[2*tid] = a; ph[2*tid+1] = b2;
    a.x = l0; a.y = l1; b2.x = l2; b2.y = l3;
    pl[2*tid] = a; pl[2*tid+1] = b2;
}

// ================== W transpose + bf16 split =======================
__global__ void wt_kernel(const float* __restrict__ W) {
    __shared__ float tile[32][33];
    int n0 = blockIdx.x * 32, k0 = blockIdx.y * 32;
    int tx = threadIdx.x, ty = threadIdx.y;   // 32 x 8
    #pragma unroll
    for (int j = 0; j < 4; ++j)
        tile[ty + 8*j][tx] = W[(size_t)(k0 + ty + 8*j) * NOUT + n0 + tx];
    __syncthreads();
    #pragma unroll
    for (int j = 0; j < 4; ++j) {
        float v = tile[tx][ty + 8*j];
        __nv_bfloat16 h = __float2bfloat16_rn(v);
        size_t o = (size_t)(n0 + ty + 8*j) * DM + k0 + tx;
        g_whi[o] = h;
        g_wlo[o] = __float2bfloat16_rn(v - __bfloat162float(h));
    }
}

// ================ mma.sync bf16-split GEMM =========================
// g_pT[n][s] = (Ahi*Bhi + Alo*Bhi + Ahi*Blo)[s][n] + bias[n]
// 8 warps: warp grid 4(m) x 2(n); warp tile 32m x 48n; k16 per HMMA.
// Product-major MMA order (12 independent accs between same-acc reuse)
// + 3-stage cp.async ring with ONE __syncthreads per k-chunk.
__global__ __launch_bounds__(256, 2) void gemm_kernel(const float* __restrict__ bias) {
    extern __shared__ char smem[];
    uint32_t sb = smem_to_u32(smem);
    int tid = threadIdx.x, wid = tid >> 5, lane = tid & 31;
    int n0 = blockIdx.x * BN, m0 = blockIdx.y * BM;

    // ---- cp.async staging of one 35.8KB chunk (A hi/lo, B hi/lo) ----
    auto stage = [&](int ch, int s) {
        uint32_t base = sb + s * STAGE;
        int kb = ch * BK;
        #pragma unroll
        for (int v = 0; v < NCOPY / 256; ++v) {
            int idx = tid + v * 256;
            const void* src; uint32_t off;
            if (idx < 1024) {                       // A: 2 mats x 128 rows x 4 vec16
                int mat = idx >> 9;
                int i = idx & 511;
                int r = i >> 2, c = i & 3;
                const __nv_bfloat16* g = mat ? g_alo : g_ahi;
                src = g + (size_t)(m0 + r) * DM + kb + c * 8;
                off = (mat ? R_ALO : R_AHI) + r * APITCH + c * 16;
            } else {                                // B: 2 mats x 96 rows x 4 vec16
                int b = idx - 1024;
                int mat = b / 384; int rb = b - mat * 384;
                int r = rb >> 2, c = rb & 3;
                const __nv_bfloat16* g = mat ? g_wlo : g_whi;
                src = g + (size_t)(n0 + r) * DM + kb + c * 8;
                off = (mat ? R_BLO : R_BHI) + r * APITCH + c * 16;
            }
            cpasync16(base + off, src);
        }
        CP_COMMIT();
    };

    stage(0, 0);
    stage(1, 1);

    int wm = (wid >> 1) * 32;          // warp m-offset in CTA tile
    int wn = (wid & 1) * 48;           // warp n-offset
    // ldmatrix per-lane address components (pitch-80 rows -> conflict-free)
    uint32_t aoff = (uint32_t)(wm + (lane & 15)) * APITCH + (uint32_t)(lane >> 4) * 16;
    uint32_t boff = (uint32_t)(wn + (lane & 7) + ((lane >> 4) & 1) * 8) * APITCH
                  + (uint32_t)((lane >> 3) & 1) * 16;

    float acc[2][6][4];
    #pragma unroll
    for (int i = 0; i < 2; ++i)
        #pragma unroll
        for (int j = 0; j < 6; ++j)
            #pragma unroll
            for (int q = 0; q < 4; ++q) acc[i][j][q] = 0.f;

    int slot = 0;        // it % 3
    int nslot = 2;       // (it+2) % 3
    for (int it = 0; it < NIT; ++it) {
        CP_WAIT1();              // chunk `it` landed (chunks it+1[, it+2] in flight)
        __syncthreads();         // all warps done with slot (it+2)%3 (read at it-1)
        if (it + 2 < NIT) stage(it + 2, nslot);
        uint32_t base = sb + slot * STAGE;
        #pragma unroll
        for (int ki = 0; ki < 2; ++ki) {
            uint32_t ah[2][4], al[2][4], bh[6][2], bl[6][2];
            uint32_t ka = base + ki * 32 + aoff;
            LDSM_X4(ah[0][0], ah[0][1], ah[0][2], ah[0][3], ka + R_AHI);
            LDSM_X4(ah[1][0], ah[1][1], ah[1][2], ah[1][3], ka + R_AHI + 16 * APITCH);
            LDSM_X4(al[0][0], al[0][1], al[0][2], al[0][3], ka + R_ALO);
            LDSM_X4(al[1][0], al[1][1], al[1][2], al[1][3], ka + R_ALO + 16 * APITCH);
            uint32_t kb2 = base + ki * 32 + boff;
            #pragma unroll
            for (int pj = 0; pj < 3; ++pj) {
                LDSM_X4(bh[2*pj][0], bh[2*pj][1], bh[2*pj+1][0], bh[2*pj+1][1],
                        kb2 + R_BHI + pj * 16 * APITCH);
                LDSM_X4(bl[2*pj][0], bl[2*pj][1], bl[2*pj+1][0], bl[2*pj+1][1],
                        kb2 + R_BLO + pj * 16 * APITCH);
            }
            // product-major: 12 independent accumulators between reuse
            #pragma unroll
            for (int mi = 0; mi < 2; ++mi)
                #pragma unroll
                for (int nj = 0; nj < 6; ++nj)
                    MMA16816(acc[mi][nj], ah[mi], bh[nj]);
            #pragma unroll
            for (int mi = 0; mi < 2; ++mi)
                #pragma unroll
                for (int nj = 0; nj < 6; ++nj)
                    MMA16816(acc[mi][nj], al[mi], bh[nj]);
            #pragma unroll
            for (int mi = 0; mi < 2; ++mi)
                #pragma unroll
                for (int nj = 0; nj < 6; ++nj)
                    MMA16816(acc[mi][nj], ah[mi], bl[nj]);
        }
        slot = (slot == 2) ? 0 : slot + 1;
        nslot = (nslot == 2) ? 0 : nslot + 1;
    }

    // ---- epilogue: frags -> g_pT (transposed, +bias) ----
    int qr = lane >> 2, qc = (lane & 3) * 2;
    #pragma unroll
    for (int mi = 0; mi < 2; ++mi) {
        int m = m0 + wm + mi * 16 + qr;
        #pragma unroll
        for (int nj = 0; nj < 6; ++nj) {
            int n = n0 + wn + nj * 8 + qc;
            float b0 = bias[n], b1 = bias[n + 1];
            g_pT[(size_t)n       * SEQ + m]     = acc[mi][nj][0] + b0;
            g_pT[(size_t)(n + 1) * SEQ + m]     = acc[mi][nj][1] + b1;
            g_pT[(size_t)n       * SEQ + m + 8] = acc[mi][nj][2] + b0;
            g_pT[(size_t)(n + 1) * SEQ + m + 8] = acc[mi][nj][3] + b1;
        }
    }
}

// ============== Fused transform + spring scatter ===================
// One thread per (t0, imu) site: computes oscillator params (MUFU work
// hidden under the FMA-bound recurrence loop), emits the 4 output
// channels, then runs the 300-step complex recurrence with warp-private
// volatile smem windows (lane i, step t -> slot i+t: distinct within
// lockstep warp; volatile forbids cross-iteration LDS batching).
__global__ __launch_bounds__(256) void spring_kernel(float* __restrict__ out) {
    __shared__ float buf[8][336];
    int tid = threadIdx.x;
    int imu = blockIdx.y;
    int c0  = blockIdx.x * 256;
    int t0  = c0 + tid;

    for (int i = tid; i < 8 * 336; i += 256) ((float*)buf)[i] = 0.f;

    // ---- coalesced param loads from transposed GEMM output ----
    const float* col = g_pT + (size_t)imu * SEQ + t0;   // stride PLANE per noise row
    float p0  = col[0*PLANE],  p1  = col[1*PLANE],  p2  = col[2*PLANE],  p3 = col[3*PLANE];
    float p4  = col[4*PLANE],  p5  = col[5*PLANE],  p6  = col[6*PLANE],  p7 = col[7*PLANE];
    float p8  = col[8*PLANE],  p9  = col[9*PLANE],  p10 = col[10*PLANE], p11 = col[11*PLANE];

    // ---- direct output channels ----
    size_t ob = (size_t)imu * SEQ + t0;
    out[1 * PLANE + ob] = p8;
    out[2 * PLANE + ob] = softplusf(p9);
    out[3 * PLANE + ob] = p10;
    out[4 * PLANE + ob] = softplusf(p11);

    // ---- oscillator params: omega = sqrt(4k-d^2)/2 == sqrt(softplus(p0)) ----
    float om1 = sqrtf(softplusf(p0));
    float e1  = expf(-0.5f * softplusf(p1));
    float om2 = sqrtf(softplusf(p2));
    float e2  = expf(-0.5f * softplusf(p3));
    float sph1, cph1; sincosf(p6, &sph1, &cph1);
    float sph2, cph2; sincosf(p7, &sph2, &cph2);
    float so1, co1;   sincosf(om1, &so1, &co1);
    float so2, co2;   sincosf(om2, &so2, &co2);

    // pack both oscillators into f32x2 lanes
    ull Ur  = fpack2(p4 * cph1, p5 * cph2);
    ull Ui  = fpack2(p4 * sph1, p5 * sph2);
    ull Rr  = fpack2(e1 * co1,  e2 * co2);
    ull Ri  = fpack2(e1 * so1,  e2 * so2);
    ull Rin = fpack2(-e1 * so1, -e2 * so2);

    __syncthreads();

    volatile float* wb = buf[tid >> 5];
    int l = tid & 31;

    #pragma unroll 4
    for (int t = 0; t < TSTEPS; ++t) {
        float2 ui = funpack2(Ui);
        wb[l + t] = wb[l + t] + (ui.x + ui.y);
        ull t1 = fmul2(Ui, Rin);
        ull t2 = fmul2(Ui, Rr);
        ull nr = ffma2(Ur, Rr, t1);
        ull ni = ffma2(Ur, Ri, t2);
        Ur = nr; Ui = ni;
    }
    __syncthreads();

    // merge 8 overlapping warp windows -> block output span [c0, c0+554]
    for (int o = tid; o < 555; o += 256) {
        float v = 0.f;
        #pragma unroll
        for (int w = 0; w < 8; ++w) {
            int idx = o - (w << 5);
            if (idx >= 0 && idx <= 330) v += buf[w][idx];
        }
        int pos = c0 + o;
        if (pos < SEQ) atomicAdd(out + (size_t)imu * SEQ + pos, v);
    }
}

// =========================== launch ================================
extern "C" void kernel_launch(void* const* d_in, const int* in_sizes, int n_in,
                              void* d_out, int out_size) {
    const float* hs    = (const float*)d_in[0];
    const float* gamma = (const float*)d_in[1];
    const float* beta  = (const float*)d_in[2];
    const float* W     = (const float*)d_in[3];
    const float* b     = (const float*)d_in[4];
    float* out = (float*)d_out;

    cudaFuncSetAttribute(gemm_kernel, cudaFuncAttributeMaxDynamicSharedMemorySize, SMEM_TOT);

    zero_kernel<<<PLANE / 1024, 256>>>(out);                       // #1
    ln_kernel<<<SEQ, 256>>>(hs, gamma, beta);                      // #2
    wt_kernel<<<dim3(NOUT / 32, DM / 32), dim3(32, 8)>>>(W);       // #3
    gemm_kernel<<<dim3(NOUT / BN, SEQ / BM), 256, SMEM_TOT>>>(b);  // #4 (ncu target)
    spring_kernel<<<dim3(SEQ / 256, NIMU), 256>>>(out);            // #5
}